// round 13
// baseline (speedup 1.0000x reference)
#include <cuda_runtime.h>
#include <cuda_fp16.h>
#include <math.h>

#define NN 150000
#define UU 100000
#define II 50000
#define DD 64
#define EE 2000000
#define LL 3
#define SCAN_B 1024
#define NBLK ((NN + SCAN_B - 1) / SCAN_B)   // 147

__device__ __forceinline__ unsigned int h2_as_u32(__half2 h) {
    return *reinterpret_cast<unsigned int*>(&h);
}
__device__ __forceinline__ __half2 u32_as_h2(unsigned int u) {
    return *reinterpret_cast<__half2*>(&u);
}

// -------- device scratch (no allocations allowed) --------
__device__ float   g_curA[NN * DD];
__device__ float   g_curB[NN * DD];
__device__ float   g_curS[NN * DD];      // dis ⊙ cur, fp32 (layer1 gather operand)
__device__ float   g_gnn[NN * DD];
__device__ __half2 g_gnh[NN * 32];       // normalized gnn, fp16 (layer2 score gather)
__device__ float   g_invn[NN];
__device__ float   g_dis[NN];
__device__ int     g_deg[NN];
__device__ int     g_rowptr[NN + 1];
__device__ int     g_cursor[NN];
__device__ int     g_ecol[EE];
__device__ int     g_bsum[NBLK + 1];
__device__ int     g_boff[NBLK + 1];

// ---------------- setup kernels ----------------

__global__ void hist_kernel(const int* __restrict__ rows) {
    int e = blockIdx.x * blockDim.x + threadIdx.x;
    if (e < EE) atomicAdd(&g_deg[rows[e]], 1);
}

__global__ void scan1_kernel() {
    __shared__ int s[SCAN_B];
    int i = blockIdx.x * SCAN_B + threadIdx.x;
    int v = (i < NN) ? g_deg[i] : 0;
    if (i < NN) g_dis[i] = v > 0 ? rsqrtf((float)v) : 0.f;
    s[threadIdx.x] = v;
    __syncthreads();
    #pragma unroll
    for (int off = 1; off < SCAN_B; off <<= 1) {
        int t = (threadIdx.x >= off) ? s[threadIdx.x - off] : 0;
        __syncthreads();
        s[threadIdx.x] += t;
        __syncthreads();
    }
    if (i < NN) g_rowptr[i + 1] = s[threadIdx.x];
    if (threadIdx.x == SCAN_B - 1) g_bsum[blockIdx.x] = s[SCAN_B - 1];
}

__global__ void scan2_kernel() {
    __shared__ int s[256];
    int t = threadIdx.x;
    int v = (t < NBLK) ? g_bsum[t] : 0;
    s[t] = v;
    __syncthreads();
    #pragma unroll
    for (int off = 1; off < 256; off <<= 1) {
        int x = (t >= off) ? s[t - off] : 0;
        __syncthreads();
        s[t] += x;
        __syncthreads();
    }
    if (t < NBLK) g_boff[t] = s[t] - v;
}

__global__ void scan3_kernel() {
    int i = blockIdx.x * blockDim.x + threadIdx.x;
    if (i == 0) g_rowptr[0] = 0;
    if (i < NN) {
        int fin = g_rowptr[i + 1] + g_boff[i / SCAN_B];
        g_rowptr[i + 1] = fin;
        g_cursor[i] = fin - g_deg[i];
    }
}

__global__ void scatter_kernel(const int* __restrict__ rows, const int* __restrict__ cols) {
    int e = blockIdx.x * blockDim.x + threadIdx.x;
    if (e >= EE) return;
    int r = rows[e];
    int pos = atomicAdd(&g_cursor[r], 1);
    g_ecol[pos] = cols[e];
}

__global__ void init_kernel(const float* __restrict__ user_emb,
                            const float* __restrict__ item_emb,
                            float* __restrict__ out) {
    int i = blockIdx.x * blockDim.x + threadIdx.x;
    if (i < NN * DD) {
        float v = (i < UU * DD) ? user_emb[i] : item_emb[i - UU * DD];
        g_curA[i] = v;
        g_curS[i] = v * g_dis[i >> 6];
        out[i] = v;
    }
}

// ---------------- per-layer kernels ----------------
// 2 rows per warp: lanes 0-15 -> row 2w, lanes 16-31 -> row 2w+1
// each lane covers 4 consecutive floats (float4, LDG.128)

// gather-sum: gnn[r] = dis[r] * sum_e curS[c_e]; epilogue: invn + fp16 normalized row
__global__ void __launch_bounds__(256)
layer1_kernel(const float* __restrict__ curS) {
    int gw = (blockIdx.x * blockDim.x + threadIdx.x) >> 5;
    int lane = threadIdx.x & 31;
    int half = lane >> 4, sub = lane & 15;
    int r = gw * 2 + half;
    if (r >= NN) return;
    int start = g_rowptr[r];
    int end   = g_rowptr[r + 1];
    float4 a0 = make_float4(0.f, 0.f, 0.f, 0.f);
    float4 a1 = make_float4(0.f, 0.f, 0.f, 0.f);
    int j = start;
    for (; j + 3 < end; j += 4) {
        int c0 = __ldg(g_ecol + j);
        int c1 = __ldg(g_ecol + j + 1);
        int c2 = __ldg(g_ecol + j + 2);
        int c3 = __ldg(g_ecol + j + 3);
        float4 v0 = __ldg(((const float4*)(curS + (size_t)c0 * DD)) + sub);
        float4 v1 = __ldg(((const float4*)(curS + (size_t)c1 * DD)) + sub);
        float4 v2 = __ldg(((const float4*)(curS + (size_t)c2 * DD)) + sub);
        float4 v3 = __ldg(((const float4*)(curS + (size_t)c3 * DD)) + sub);
        a0.x += v0.x + v2.x;  a0.y += v0.y + v2.y;
        a0.z += v0.z + v2.z;  a0.w += v0.w + v2.w;
        a1.x += v1.x + v3.x;  a1.y += v1.y + v3.y;
        a1.z += v1.z + v3.z;  a1.w += v1.w + v3.w;
    }
    for (; j < end; j++) {
        int c = __ldg(g_ecol + j);
        float4 v = __ldg(((const float4*)(curS + (size_t)c * DD)) + sub);
        a0.x += v.x;  a0.y += v.y;  a0.z += v.z;  a0.w += v.w;
    }
    float dr = g_dis[r];
    float4 ax;
    ax.x = (a0.x + a1.x) * dr;
    ax.y = (a0.y + a1.y) * dr;
    ax.z = (a0.z + a1.z) * dr;
    ax.w = (a0.w + a1.w) * dr;
    ((float4*)(g_gnn + (size_t)r * DD))[sub] = ax;
    float ss = ax.x * ax.x + ax.y * ax.y + ax.z * ax.z + ax.w * ax.w;
    #pragma unroll
    for (int o = 8; o > 0; o >>= 1) ss += __shfl_xor_sync(0xFFFFFFFFu, ss, o);
    float inv = 1.0f / fmaxf(sqrtf(ss), 1e-12f);
    if (sub == 0) g_invn[r] = inv;
    uint2 ph;
    ph.x = h2_as_u32(__floats2half2_rn(ax.x * inv, ax.y * inv));
    ph.y = h2_as_u32(__floats2half2_rn(ax.z * inv, ax.w * inv));
    ((uint2*)g_gnh)[(size_t)r * 16 + sub] = ph;
}

// fused: scores + rowsum + fine + finalize
__global__ void __launch_bounds__(256)
layer2_kernel(const float* __restrict__ cur_old,
              float* __restrict__ cur_new,
              float* __restrict__ out, int layer) {
    int gw = (blockIdx.x * blockDim.x + threadIdx.x) >> 5;
    int lane = threadIdx.x & 31;
    int half = lane >> 4, sub = lane & 15;
    int r = gw * 2 + half;
    if (r >= NN) return;
    int start = g_rowptr[r];
    int end   = g_rowptr[r + 1];
    float4 gfull = ((const float4*)(g_gnn + (size_t)r * DD))[sub];
    float invr = g_invn[r];
    float4 gr;
    gr.x = gfull.x * invr;  gr.y = gfull.y * invr;
    gr.z = gfull.z * invr;  gr.w = gfull.w * invr;

    float rowsum = 0.f;
    float4 f = make_float4(0.f, 0.f, 0.f, 0.f);
    int j = start;
    for (; j + 1 < end; j += 2) {
        int c0 = __ldg(g_ecol + j);
        int c1 = __ldg(g_ecol + j + 1);
        uint2 q0 = __ldg(((const uint2*)g_gnh) + (size_t)c0 * 16 + sub);
        uint2 q1 = __ldg(((const uint2*)g_gnh) + (size_t)c1 * 16 + sub);
        float4 v0 = __ldg(((const float4*)(cur_old + (size_t)c0 * DD)) + sub);
        float4 v1 = __ldg(((const float4*)(cur_old + (size_t)c1 * DD)) + sub);
        float2 qa0 = __half22float2(u32_as_h2(q0.x));
        float2 qb0 = __half22float2(u32_as_h2(q0.y));
        float2 qa1 = __half22float2(u32_as_h2(q1.x));
        float2 qb1 = __half22float2(u32_as_h2(q1.y));
        float d0 = gr.x * qa0.x + gr.y * qa0.y + gr.z * qb0.x + gr.w * qb0.y;
        float d1 = gr.x * qa1.x + gr.y * qa1.y + gr.z * qb1.x + gr.w * qb1.y;
        #pragma unroll
        for (int o = 8; o > 0; o >>= 1) {
            d0 += __shfl_xor_sync(0xFFFFFFFFu, d0, o);
            d1 += __shfl_xor_sync(0xFFFFFFFFu, d1, o);
        }
        float s0 = fmaf(d0, 0.5f, 0.5f);
        float s1 = fmaf(d1, 0.5f, 0.5f);
        rowsum += s0 + s1;
        f.x = fmaf(s0, v0.x, f.x);  f.y = fmaf(s0, v0.y, f.y);
        f.z = fmaf(s0, v0.z, f.z);  f.w = fmaf(s0, v0.w, f.w);
        f.x = fmaf(s1, v1.x, f.x);  f.y = fmaf(s1, v1.y, f.y);
        f.z = fmaf(s1, v1.z, f.z);  f.w = fmaf(s1, v1.w, f.w);
    }
    if (j < end) {
        int c = __ldg(g_ecol + j);
        uint2 q = __ldg(((const uint2*)g_gnh) + (size_t)c * 16 + sub);
        float4 v = __ldg(((const float4*)(cur_old + (size_t)c * DD)) + sub);
        float2 qa = __half22float2(u32_as_h2(q.x));
        float2 qb = __half22float2(u32_as_h2(q.y));
        float d = gr.x * qa.x + gr.y * qa.y + gr.z * qb.x + gr.w * qb.y;
        #pragma unroll
        for (int o = 8; o > 0; o >>= 1) d += __shfl_xor_sync(0xFFFFFFFFu, d, o);
        float s = fmaf(d, 0.5f, 0.5f);
        rowsum += s;
        f.x = fmaf(s, v.x, f.x);  f.y = fmaf(s, v.y, f.y);
        f.z = fmaf(s, v.z, f.z);  f.w = fmaf(s, v.w, f.w);
    }

    float dinv = rowsum > 0.f ? 1.0f / rowsum : 0.f;
    f.x *= dinv;  f.y *= dinv;  f.z *= dinv;  f.w *= dinv;

    // fine slice -> out (stacked: [acc(N,D)][user_fine(L,U,D)][item_fine(L,I,D)])
    size_t fpos;
    if (r < UU)
        fpos = (size_t)NN * DD + (size_t)layer * UU * DD + (size_t)r * DD;
    else
        fpos = (size_t)NN * DD + (size_t)LL * UU * DD + (size_t)layer * II * DD
             + (size_t)(r - UU) * DD;
    ((float4*)(out + fpos))[sub] = f;

    float4 cn;                                      // cur_next = gnn + fine
    cn.x = gfull.x + f.x;  cn.y = gfull.y + f.y;
    cn.z = gfull.z + f.z;  cn.w = gfull.w + f.w;
    ((float4*)(cur_new + (size_t)r * DD))[sub] = cn;

    float dr = g_dis[r];                            // curS_next = dis ⊙ cur_next
    float4 cs;
    cs.x = cn.x * dr;  cs.y = cn.y * dr;  cs.z = cn.z * dr;  cs.w = cn.w * dr;
    ((float4*)(g_curS + (size_t)r * DD))[sub] = cs;

    float4* o = (float4*)(out + (size_t)r * DD);    // acc += cur_next
    float4 ov = o[sub];
    ov.x += cn.x;  ov.y += cn.y;  ov.z += cn.z;  ov.w += cn.w;
    o[sub] = ov;
}

// ---------------- launch ----------------
extern "C" void kernel_launch(void* const* d_in, const int* in_sizes, int n_in,
                              void* d_out, int out_size) {
    const float* user_emb = (const float*)d_in[0];
    const float* item_emb = (const float*)d_in[1];
    const int*   rows     = (const int*)d_in[2];
    const int*   cols     = (const int*)d_in[3];
    float* out = (float*)d_out;

    void *p_deg, *p_curA, *p_curB, *p_curS;
    cudaGetSymbolAddress(&p_deg, g_deg);
    cudaGetSymbolAddress(&p_curA, g_curA);
    cudaGetSymbolAddress(&p_curB, g_curB);
    cudaGetSymbolAddress(&p_curS, g_curS);

    cudaStream_t s = 0;
    const int TB = 256;
    const int grid_E    = (EE + TB - 1) / TB;
    const int grid_N    = (NN + TB - 1) / TB;
    const int grid_ND   = (NN * DD + TB - 1) / TB;
    const int nwarps    = (NN + 1) / 2;                    // 2 rows per warp
    const int grid_Row2 = (nwarps * 32 + TB - 1) / TB;

    cudaMemsetAsync(p_deg, 0, NN * sizeof(int), s);
    hist_kernel<<<grid_E, TB, 0, s>>>(rows);
    scan1_kernel<<<NBLK, SCAN_B, 0, s>>>();
    scan2_kernel<<<1, 256, 0, s>>>();
    scan3_kernel<<<grid_N, TB, 0, s>>>();
    scatter_kernel<<<grid_E, TB, 0, s>>>(rows, cols);
    init_kernel<<<grid_ND, TB, 0, s>>>(user_emb, item_emb, out);

    float* bufA = (float*)p_curA;
    float* bufB = (float*)p_curB;
    for (int l = 0; l < LL; l++) {
        layer1_kernel<<<grid_Row2, TB, 0, s>>>((const float*)p_curS);
        layer2_kernel<<<grid_Row2, TB, 0, s>>>(bufA, bufB, out, l);
        float* t = bufA; bufA = bufB; bufB = t;
    }
}

// round 14
// speedup vs baseline: 1.3004x; 1.3004x over previous
#include <cuda_runtime.h>
#include <cuda_fp16.h>
#include <math.h>

#define NN 150000
#define UU 100000
#define II 50000
#define DD 64
#define EE 2000000
#define LL 3
#define SCAN_B 1024
#define NBLK ((NN + SCAN_B - 1) / SCAN_B)   // 147

// -------- device scratch (no allocations allowed) --------
__device__ float   g_curA[NN * DD];
__device__ float   g_curB[NN * DD];
__device__ float   g_curS[NN * DD];        // dis ⊙ cur, fp32 (layer1 gather operand)
__device__ float   g_gnn[NN * DD];
__device__ __half2 g_gnh[NN * 32];         // normalized gnn, fp16 (layer2 score gather)
__device__ float   g_invn[NN];
__device__ float   g_dis[NN];
__device__ int     g_deg[NN];
__device__ int     g_rowptr[NN + 1];
__device__ int     g_cursor[NN];
__device__ int     g_ecol[EE + 8];          // +8 pad: unconditional batch index loads
__device__ int     g_bsum[NBLK + 1];
__device__ int     g_boff[NBLK + 1];

// ---------------- setup kernels ----------------

__global__ void hist_kernel(const int* __restrict__ rows) {
    int e = blockIdx.x * blockDim.x + threadIdx.x;
    if (e < EE) atomicAdd(&g_deg[rows[e]], 1);
}

__global__ void scan1_kernel() {
    __shared__ int s[SCAN_B];
    int i = blockIdx.x * SCAN_B + threadIdx.x;
    int v = (i < NN) ? g_deg[i] : 0;
    if (i < NN) g_dis[i] = v > 0 ? rsqrtf((float)v) : 0.f;
    s[threadIdx.x] = v;
    __syncthreads();
    #pragma unroll
    for (int off = 1; off < SCAN_B; off <<= 1) {
        int t = (threadIdx.x >= off) ? s[threadIdx.x - off] : 0;
        __syncthreads();
        s[threadIdx.x] += t;
        __syncthreads();
    }
    if (i < NN) g_rowptr[i + 1] = s[threadIdx.x];
    if (threadIdx.x == SCAN_B - 1) g_bsum[blockIdx.x] = s[SCAN_B - 1];
}

__global__ void scan2_kernel() {
    __shared__ int s[256];
    int t = threadIdx.x;
    int v = (t < NBLK) ? g_bsum[t] : 0;
    s[t] = v;
    __syncthreads();
    #pragma unroll
    for (int off = 1; off < 256; off <<= 1) {
        int x = (t >= off) ? s[t - off] : 0;
        __syncthreads();
        s[t] += x;
        __syncthreads();
    }
    if (t < NBLK) g_boff[t] = s[t] - v;
}

__global__ void scan3_kernel() {
    int i = blockIdx.x * blockDim.x + threadIdx.x;
    if (i == 0) g_rowptr[0] = 0;
    if (i < NN) {
        int fin = g_rowptr[i + 1] + g_boff[i / SCAN_B];
        g_rowptr[i + 1] = fin;
        g_cursor[i] = fin - g_deg[i];
    }
}

__global__ void scatter_kernel(const int* __restrict__ rows, const int* __restrict__ cols) {
    int e = blockIdx.x * blockDim.x + threadIdx.x;
    if (e >= EE) return;
    int r = rows[e];
    int pos = atomicAdd(&g_cursor[r], 1);
    g_ecol[pos] = cols[e];
}

__global__ void init_kernel(const float* __restrict__ user_emb,
                            const float* __restrict__ item_emb,
                            float* __restrict__ out) {
    int i = blockIdx.x * blockDim.x + threadIdx.x;
    if (i < NN * DD) {
        float v = (i < UU * DD) ? user_emb[i] : item_emb[i - UU * DD];
        g_curA[i] = v;
        g_curS[i] = v * g_dis[i >> 6];
        out[i] = v;
    }
}

// ---------------- per-layer kernels ----------------

// warp-per-row gather-sum: gnn[r] = dis[r] * sum_e curS[c_e]
// predicated 8-wide batches (MLP=8), no tail loop
__global__ void __launch_bounds__(256)
layer1_kernel(const float* __restrict__ curS) {
    int w = (blockIdx.x * blockDim.x + threadIdx.x) >> 5;
    int lane = threadIdx.x & 31;
    if (w >= NN) return;
    int start = g_rowptr[w];
    int end   = g_rowptr[w + 1];
    float ax0 = 0.f, ay0 = 0.f, ax1 = 0.f, ay1 = 0.f;
    float ax2 = 0.f, ay2 = 0.f, ax3 = 0.f, ay3 = 0.f;
    const float2 z = make_float2(0.f, 0.f);
    for (int j = start; j < end; j += 8) {
        int rem = end - j;                     // >= 1
        int c0 = __ldg(g_ecol + j);
        int c1 = __ldg(g_ecol + j + 1);
        int c2 = __ldg(g_ecol + j + 2);
        int c3 = __ldg(g_ecol + j + 3);
        int c4 = __ldg(g_ecol + j + 4);
        int c5 = __ldg(g_ecol + j + 5);
        int c6 = __ldg(g_ecol + j + 6);
        int c7 = __ldg(g_ecol + j + 7);
        float2 v0 =            __ldg(((const float2*)(curS + (size_t)c0 * DD)) + lane);
        float2 v1 = rem > 1 ? __ldg(((const float2*)(curS + (size_t)c1 * DD)) + lane) : z;
        float2 v2 = rem > 2 ? __ldg(((const float2*)(curS + (size_t)c2 * DD)) + lane) : z;
        float2 v3 = rem > 3 ? __ldg(((const float2*)(curS + (size_t)c3 * DD)) + lane) : z;
        float2 v4 = rem > 4 ? __ldg(((const float2*)(curS + (size_t)c4 * DD)) + lane) : z;
        float2 v5 = rem > 5 ? __ldg(((const float2*)(curS + (size_t)c5 * DD)) + lane) : z;
        float2 v6 = rem > 6 ? __ldg(((const float2*)(curS + (size_t)c6 * DD)) + lane) : z;
        float2 v7 = rem > 7 ? __ldg(((const float2*)(curS + (size_t)c7 * DD)) + lane) : z;
        ax0 += v0.x + v4.x;  ay0 += v0.y + v4.y;
        ax1 += v1.x + v5.x;  ay1 += v1.y + v5.y;
        ax2 += v2.x + v6.x;  ay2 += v2.y + v6.y;
        ax3 += v3.x + v7.x;  ay3 += v3.y + v7.y;
    }
    float dr = g_dis[w];
    float ax = ((ax0 + ax1) + (ax2 + ax3)) * dr;
    float ay = ((ay0 + ay1) + (ay2 + ay3)) * dr;
    ((float2*)(g_gnn + (size_t)w * DD))[lane] = make_float2(ax, ay);
    float ss = ax * ax + ay * ay;
    #pragma unroll
    for (int o = 16; o > 0; o >>= 1) ss += __shfl_xor_sync(0xFFFFFFFFu, ss, o);
    float inv = 1.0f / fmaxf(sqrtf(ss), 1e-12f);
    if (lane == 0) g_invn[w] = inv;
    g_gnh[(size_t)w * 32 + lane] = __floats2half2_rn(ax * inv, ay * inv);
}

// warp-per-row fused: scores (fp16 c-side) + rowsum + fine + finalize  (R4 layout)
__global__ void __launch_bounds__(256)
layer2_kernel(const float* __restrict__ cur_old,
              float* __restrict__ cur_new,
              float* __restrict__ out, int layer) {
    int w = (blockIdx.x * blockDim.x + threadIdx.x) >> 5;
    int lane = threadIdx.x & 31;
    if (w >= NN) return;
    int start = g_rowptr[w];
    int end   = g_rowptr[w + 1];
    float2 gfull = ((const float2*)(g_gnn + (size_t)w * DD))[lane];
    float invr = g_invn[w];
    float grx = gfull.x * invr, gry = gfull.y * invr;

    float rowsum = 0.f, fx = 0.f, fy = 0.f;
    int j = start;
    for (; j + 3 < end; j += 4) {
        int c0 = __ldg(g_ecol + j);
        int c1 = __ldg(g_ecol + j + 1);
        int c2 = __ldg(g_ecol + j + 2);
        int c3 = __ldg(g_ecol + j + 3);
        float2 q0 = __half22float2(__ldg(g_gnh + (size_t)c0 * 32 + lane));
        float2 q1 = __half22float2(__ldg(g_gnh + (size_t)c1 * 32 + lane));
        float2 q2 = __half22float2(__ldg(g_gnh + (size_t)c2 * 32 + lane));
        float2 q3 = __half22float2(__ldg(g_gnh + (size_t)c3 * 32 + lane));
        float2 v0 = __ldg(((const float2*)(cur_old + (size_t)c0 * DD)) + lane);
        float2 v1 = __ldg(((const float2*)(cur_old + (size_t)c1 * DD)) + lane);
        float2 v2 = __ldg(((const float2*)(cur_old + (size_t)c2 * DD)) + lane);
        float2 v3 = __ldg(((const float2*)(cur_old + (size_t)c3 * DD)) + lane);
        float d0 = grx * q0.x + gry * q0.y;
        float d1 = grx * q1.x + gry * q1.y;
        float d2 = grx * q2.x + gry * q2.y;
        float d3 = grx * q3.x + gry * q3.y;
        #pragma unroll
        for (int o = 16; o > 0; o >>= 1) {
            d0 += __shfl_xor_sync(0xFFFFFFFFu, d0, o);
            d1 += __shfl_xor_sync(0xFFFFFFFFu, d1, o);
            d2 += __shfl_xor_sync(0xFFFFFFFFu, d2, o);
            d3 += __shfl_xor_sync(0xFFFFFFFFu, d3, o);
        }
        float s0 = fmaf(d0, 0.5f, 0.5f);
        float s1 = fmaf(d1, 0.5f, 0.5f);
        float s2 = fmaf(d2, 0.5f, 0.5f);
        float s3 = fmaf(d3, 0.5f, 0.5f);
        rowsum += (s0 + s1) + (s2 + s3);
        fx = fmaf(s0, v0.x, fx);  fy = fmaf(s0, v0.y, fy);
        fx = fmaf(s1, v1.x, fx);  fy = fmaf(s1, v1.y, fy);
        fx = fmaf(s2, v2.x, fx);  fy = fmaf(s2, v2.y, fy);
        fx = fmaf(s3, v3.x, fx);  fy = fmaf(s3, v3.y, fy);
    }
    for (; j < end; j++) {
        int c = __ldg(g_ecol + j);
        float2 q = __half22float2(__ldg(g_gnh + (size_t)c * 32 + lane));
        float2 v = __ldg(((const float2*)(cur_old + (size_t)c * DD)) + lane);
        float d = grx * q.x + gry * q.y;
        #pragma unroll
        for (int o = 16; o > 0; o >>= 1) d += __shfl_xor_sync(0xFFFFFFFFu, d, o);
        float s = fmaf(d, 0.5f, 0.5f);
        rowsum += s;
        fx = fmaf(s, v.x, fx);  fy = fmaf(s, v.y, fy);
    }

    float dinv = rowsum > 0.f ? 1.0f / rowsum : 0.f;
    fx *= dinv;
    fy *= dinv;

    // fine slice -> out (stacked: [acc(N,D)][user_fine(L,U,D)][item_fine(L,I,D)])
    size_t fpos;
    if (w < UU)
        fpos = (size_t)NN * DD + (size_t)layer * UU * DD + (size_t)w * DD;
    else
        fpos = (size_t)NN * DD + (size_t)LL * UU * DD + (size_t)layer * II * DD
             + (size_t)(w - UU) * DD;
    ((float2*)(out + fpos))[lane] = make_float2(fx, fy);

    float cx = gfull.x + fx, cy = gfull.y + fy;       // cur_next = gnn + fine
    ((float2*)(cur_new + (size_t)w * DD))[lane] = make_float2(cx, cy);

    float dr = g_dis[w];                               // curS_next = dis ⊙ cur_next
    ((float2*)(g_curS + (size_t)w * DD))[lane] = make_float2(cx * dr, cy * dr);

    float2* o = (float2*)(out + (size_t)w * DD);       // acc += cur_next
    float2 ov = o[lane];
    o[lane] = make_float2(ov.x + cx, ov.y + cy);
}

// ---------------- launch ----------------
extern "C" void kernel_launch(void* const* d_in, const int* in_sizes, int n_in,
                              void* d_out, int out_size) {
    const float* user_emb = (const float*)d_in[0];
    const float* item_emb = (const float*)d_in[1];
    const int*   rows     = (const int*)d_in[2];
    const int*   cols     = (const int*)d_in[3];
    float* out = (float*)d_out;

    void *p_deg, *p_curA, *p_curB, *p_curS;
    cudaGetSymbolAddress(&p_deg, g_deg);
    cudaGetSymbolAddress(&p_curA, g_curA);
    cudaGetSymbolAddress(&p_curB, g_curB);
    cudaGetSymbolAddress(&p_curS, g_curS);

    cudaStream_t s = 0;
    const int TB = 256;
    const int grid_E    = (EE + TB - 1) / TB;
    const int grid_N    = (NN + TB - 1) / TB;
    const int grid_ND   = (NN * DD + TB - 1) / TB;
    const int grid_RowW = (NN * 32 + TB - 1) / TB;   // warp-per-row

    cudaMemsetAsync(p_deg, 0, NN * sizeof(int), s);
    hist_kernel<<<grid_E, TB, 0, s>>>(rows);
    scan1_kernel<<<NBLK, SCAN_B, 0, s>>>();
    scan2_kernel<<<1, 256, 0, s>>>();
    scan3_kernel<<<grid_N, TB, 0, s>>>();
    scatter_kernel<<<grid_E, TB, 0, s>>>(rows, cols);
    init_kernel<<<grid_ND, TB, 0, s>>>(user_emb, item_emb, out);

    float* bufA = (float*)p_curA;
    float* bufB = (float*)p_curB;
    for (int l = 0; l < LL; l++) {
        layer1_kernel<<<grid_RowW, TB, 0, s>>>((const float*)p_curS);
        layer2_kernel<<<grid_RowW, TB, 0, s>>>(bufA, bufB, out, l);
        float* t = bufA; bufA = bufB; bufB = t;
    }
}

// round 15
// speedup vs baseline: 1.3582x; 1.0444x over previous
#include <cuda_runtime.h>
#include <cuda_fp16.h>
#include <math.h>

#define NN 150000
#define UU 100000
#define II 50000
#define DD 64
#define EE 2000000
#define LL 3
#define SCAN_B 1024
#define NBLK ((NN + SCAN_B - 1) / SCAN_B)   // 147

// -------- device scratch (no allocations allowed) --------
__device__ float   g_curA[NN * DD];
__device__ float   g_curB[NN * DD];
__device__ float   g_curS[NN * DD];        // dis ⊙ cur, fp32 (layer1 gather operand)
__device__ float   g_gnn[NN * DD];
__device__ __half2 g_gnh[NN * 32];         // normalized gnn, fp16 (layer2 score gather)
__device__ float   g_invn[NN];
__device__ float   g_dis[NN];
__device__ int     g_deg[NN];
__device__ int     g_rowptr[NN + 1];
__device__ int     g_cursor[NN];
__device__ int     g_ecol[EE];
__device__ int     g_bsum[NBLK + 1];
__device__ int     g_boff[NBLK + 1];

// ---------------- setup kernels ----------------

// 4 edges per thread, int4 index loads, 4 atomics in flight
__global__ void hist_kernel(const int* __restrict__ rows) {
    int t = blockIdx.x * blockDim.x + threadIdx.x;
    if (t >= EE / 4) return;
    int4 r = __ldg(((const int4*)rows) + t);
    atomicAdd(&g_deg[r.x], 1);
    atomicAdd(&g_deg[r.y], 1);
    atomicAdd(&g_deg[r.z], 1);
    atomicAdd(&g_deg[r.w], 1);
}

__global__ void scan1_kernel() {
    __shared__ int s[SCAN_B];
    int i = blockIdx.x * SCAN_B + threadIdx.x;
    int v = (i < NN) ? g_deg[i] : 0;
    if (i < NN) g_dis[i] = v > 0 ? rsqrtf((float)v) : 0.f;
    s[threadIdx.x] = v;
    __syncthreads();
    #pragma unroll
    for (int off = 1; off < SCAN_B; off <<= 1) {
        int t = (threadIdx.x >= off) ? s[threadIdx.x - off] : 0;
        __syncthreads();
        s[threadIdx.x] += t;
        __syncthreads();
    }
    if (i < NN) g_rowptr[i + 1] = s[threadIdx.x];
    if (threadIdx.x == SCAN_B - 1) g_bsum[blockIdx.x] = s[SCAN_B - 1];
}

__global__ void scan2_kernel() {
    __shared__ int s[256];
    int t = threadIdx.x;
    int v = (t < NBLK) ? g_bsum[t] : 0;
    s[t] = v;
    __syncthreads();
    #pragma unroll
    for (int off = 1; off < 256; off <<= 1) {
        int x = (t >= off) ? s[t - off] : 0;
        __syncthreads();
        s[t] += x;
        __syncthreads();
    }
    if (t < NBLK) g_boff[t] = s[t] - v;
}

__global__ void scan3_kernel() {
    int i = blockIdx.x * blockDim.x + threadIdx.x;
    if (i == 0) g_rowptr[0] = 0;
    if (i < NN) {
        int fin = g_rowptr[i + 1] + g_boff[i / SCAN_B];
        g_rowptr[i + 1] = fin;
        g_cursor[i] = fin - g_deg[i];
    }
}

// 4 edges per thread, int4 index loads, 4 independent atomic+store chains
__global__ void scatter_kernel(const int* __restrict__ rows, const int* __restrict__ cols) {
    int t = blockIdx.x * blockDim.x + threadIdx.x;
    if (t >= EE / 4) return;
    int4 r = __ldg(((const int4*)rows) + t);
    int4 c = __ldg(((const int4*)cols) + t);
    int p0 = atomicAdd(&g_cursor[r.x], 1);
    int p1 = atomicAdd(&g_cursor[r.y], 1);
    int p2 = atomicAdd(&g_cursor[r.z], 1);
    int p3 = atomicAdd(&g_cursor[r.w], 1);
    g_ecol[p0] = c.x;
    g_ecol[p1] = c.y;
    g_ecol[p2] = c.z;
    g_ecol[p3] = c.w;
}

__global__ void init_kernel(const float* __restrict__ user_emb,
                            const float* __restrict__ item_emb,
                            float* __restrict__ out) {
    int i = blockIdx.x * blockDim.x + threadIdx.x;
    if (i < NN * DD) {
        float v = (i < UU * DD) ? user_emb[i] : item_emb[i - UU * DD];
        g_curA[i] = v;
        g_curS[i] = v * g_dis[i >> 6];
        out[i] = v;
    }
}

// ---------------- per-layer kernels (R4 config, proven 684us) ----------------

// warp-per-row gather-sum: gnn[r] = dis[r] * sum_e curS[c_e]
// epilogue: invn + fp16 normalized row
__global__ void __launch_bounds__(256)
layer1_kernel(const float* __restrict__ curS) {
    int w = (blockIdx.x * blockDim.x + threadIdx.x) >> 5;
    int lane = threadIdx.x & 31;
    if (w >= NN) return;
    int start = g_rowptr[w];
    int end   = g_rowptr[w + 1];
    float ax0 = 0.f, ay0 = 0.f, ax1 = 0.f, ay1 = 0.f;
    int j = start;
    for (; j + 3 < end; j += 4) {
        int c0 = __ldg(g_ecol + j);
        int c1 = __ldg(g_ecol + j + 1);
        int c2 = __ldg(g_ecol + j + 2);
        int c3 = __ldg(g_ecol + j + 3);
        float2 v0 = __ldg(((const float2*)(curS + (size_t)c0 * DD)) + lane);
        float2 v1 = __ldg(((const float2*)(curS + (size_t)c1 * DD)) + lane);
        float2 v2 = __ldg(((const float2*)(curS + (size_t)c2 * DD)) + lane);
        float2 v3 = __ldg(((const float2*)(curS + (size_t)c3 * DD)) + lane);
        ax0 += v0.x + v2.x;  ay0 += v0.y + v2.y;
        ax1 += v1.x + v3.x;  ay1 += v1.y + v3.y;
    }
    for (; j < end; j++) {
        int c = __ldg(g_ecol + j);
        float2 v = __ldg(((const float2*)(curS + (size_t)c * DD)) + lane);
        ax0 += v.x;  ay0 += v.y;
    }
    float dr = g_dis[w];
    float ax = (ax0 + ax1) * dr;
    float ay = (ay0 + ay1) * dr;
    ((float2*)(g_gnn + (size_t)w * DD))[lane] = make_float2(ax, ay);
    float ss = ax * ax + ay * ay;
    #pragma unroll
    for (int o = 16; o > 0; o >>= 1) ss += __shfl_xor_sync(0xFFFFFFFFu, ss, o);
    float inv = 1.0f / fmaxf(sqrtf(ss), 1e-12f);
    if (lane == 0) g_invn[w] = inv;
    g_gnh[(size_t)w * 32 + lane] = __floats2half2_rn(ax * inv, ay * inv);
}

// warp-per-row fused: scores (fp16 c-side) + rowsum + fine + finalize
__global__ void __launch_bounds__(256)
layer2_kernel(const float* __restrict__ cur_old,
              float* __restrict__ cur_new,
              float* __restrict__ out, int layer) {
    int w = (blockIdx.x * blockDim.x + threadIdx.x) >> 5;
    int lane = threadIdx.x & 31;
    if (w >= NN) return;
    int start = g_rowptr[w];
    int end   = g_rowptr[w + 1];
    float2 gfull = ((const float2*)(g_gnn + (size_t)w * DD))[lane];
    float invr = g_invn[w];
    float grx = gfull.x * invr, gry = gfull.y * invr;

    float rowsum = 0.f, fx = 0.f, fy = 0.f;
    int j = start;
    for (; j + 3 < end; j += 4) {
        int c0 = __ldg(g_ecol + j);
        int c1 = __ldg(g_ecol + j + 1);
        int c2 = __ldg(g_ecol + j + 2);
        int c3 = __ldg(g_ecol + j + 3);
        float2 q0 = __half22float2(__ldg(g_gnh + (size_t)c0 * 32 + lane));
        float2 q1 = __half22float2(__ldg(g_gnh + (size_t)c1 * 32 + lane));
        float2 q2 = __half22float2(__ldg(g_gnh + (size_t)c2 * 32 + lane));
        float2 q3 = __half22float2(__ldg(g_gnh + (size_t)c3 * 32 + lane));
        float2 v0 = __ldg(((const float2*)(cur_old + (size_t)c0 * DD)) + lane);
        float2 v1 = __ldg(((const float2*)(cur_old + (size_t)c1 * DD)) + lane);
        float2 v2 = __ldg(((const float2*)(cur_old + (size_t)c2 * DD)) + lane);
        float2 v3 = __ldg(((const float2*)(cur_old + (size_t)c3 * DD)) + lane);
        float d0 = grx * q0.x + gry * q0.y;
        float d1 = grx * q1.x + gry * q1.y;
        float d2 = grx * q2.x + gry * q2.y;
        float d3 = grx * q3.x + gry * q3.y;
        #pragma unroll
        for (int o = 16; o > 0; o >>= 1) {
            d0 += __shfl_xor_sync(0xFFFFFFFFu, d0, o);
            d1 += __shfl_xor_sync(0xFFFFFFFFu, d1, o);
            d2 += __shfl_xor_sync(0xFFFFFFFFu, d2, o);
            d3 += __shfl_xor_sync(0xFFFFFFFFu, d3, o);
        }
        float s0 = fmaf(d0, 0.5f, 0.5f);
        float s1 = fmaf(d1, 0.5f, 0.5f);
        float s2 = fmaf(d2, 0.5f, 0.5f);
        float s3 = fmaf(d3, 0.5f, 0.5f);
        rowsum += (s0 + s1) + (s2 + s3);
        fx = fmaf(s0, v0.x, fx);  fy = fmaf(s0, v0.y, fy);
        fx = fmaf(s1, v1.x, fx);  fy = fmaf(s1, v1.y, fy);
        fx = fmaf(s2, v2.x, fx);  fy = fmaf(s2, v2.y, fy);
        fx = fmaf(s3, v3.x, fx);  fy = fmaf(s3, v3.y, fy);
    }
    for (; j < end; j++) {
        int c = __ldg(g_ecol + j);
        float2 q = __half22float2(__ldg(g_gnh + (size_t)c * 32 + lane));
        float2 v = __ldg(((const float2*)(cur_old + (size_t)c * DD)) + lane);
        float d = grx * q.x + gry * q.y;
        #pragma unroll
        for (int o = 16; o > 0; o >>= 1) d += __shfl_xor_sync(0xFFFFFFFFu, d, o);
        float s = fmaf(d, 0.5f, 0.5f);
        rowsum += s;
        fx = fmaf(s, v.x, fx);  fy = fmaf(s, v.y, fy);
    }

    float dinv = rowsum > 0.f ? 1.0f / rowsum : 0.f;
    fx *= dinv;
    fy *= dinv;

    // fine slice -> out (stacked: [acc(N,D)][user_fine(L,U,D)][item_fine(L,I,D)])
    size_t fpos;
    if (w < UU)
        fpos = (size_t)NN * DD + (size_t)layer * UU * DD + (size_t)w * DD;
    else
        fpos = (size_t)NN * DD + (size_t)LL * UU * DD + (size_t)layer * II * DD
             + (size_t)(w - UU) * DD;
    ((float2*)(out + fpos))[lane] = make_float2(fx, fy);

    float cx = gfull.x + fx, cy = gfull.y + fy;       // cur_next = gnn + fine
    ((float2*)(cur_new + (size_t)w * DD))[lane] = make_float2(cx, cy);

    float dr = g_dis[w];                               // curS_next = dis ⊙ cur_next
    ((float2*)(g_curS + (size_t)w * DD))[lane] = make_float2(cx * dr, cy * dr);

    float2* o = (float2*)(out + (size_t)w * DD);       // acc += cur_next
    float2 ov = o[lane];
    o[lane] = make_float2(ov.x + cx, ov.y + cy);
}

// ---------------- launch ----------------
extern "C" void kernel_launch(void* const* d_in, const int* in_sizes, int n_in,
                              void* d_out, int out_size) {
    const float* user_emb = (const float*)d_in[0];
    const float* item_emb = (const float*)d_in[1];
    const int*   rows     = (const int*)d_in[2];
    const int*   cols     = (const int*)d_in[3];
    float* out = (float*)d_out;

    void *p_deg, *p_curA, *p_curB, *p_curS;
    cudaGetSymbolAddress(&p_deg, g_deg);
    cudaGetSymbolAddress(&p_curA, g_curA);
    cudaGetSymbolAddress(&p_curB, g_curB);
    cudaGetSymbolAddress(&p_curS, g_curS);

    cudaStream_t s = 0;
    const int TB = 256;
    const int grid_E4   = (EE / 4 + TB - 1) / TB;    // 4 edges per thread
    const int grid_N    = (NN + TB - 1) / TB;
    const int grid_ND   = (NN * DD + TB - 1) / TB;
    const int grid_RowW = (NN * 32 + TB - 1) / TB;   // warp-per-row

    cudaMemsetAsync(p_deg, 0, NN * sizeof(int), s);
    hist_kernel<<<grid_E4, TB, 0, s>>>(rows);
    scan1_kernel<<<NBLK, SCAN_B, 0, s>>>();
    scan2_kernel<<<1, 256, 0, s>>>();
    scan3_kernel<<<grid_N, TB, 0, s>>>();
    scatter_kernel<<<grid_E4, TB, 0, s>>>(rows, cols);
    init_kernel<<<grid_ND, TB, 0, s>>>(user_emb, item_emb, out);

    float* bufA = (float*)p_curA;
    float* bufB = (float*)p_curB;
    for (int l = 0; l < LL; l++) {
        layer1_kernel<<<grid_RowW, TB, 0, s>>>((const float*)p_curS);
        layer2_kernel<<<grid_RowW, TB, 0, s>>>(bufA, bufB, out, l);
        float* t = bufA; bufA = bufB; bufB = t;
    }
}

// round 17
// speedup vs baseline: 1.3701x; 1.0088x over previous
#include <cuda_runtime.h>
#include <cuda_fp16.h>
#include <math.h>

#define NN 150000
#define UU 100000
#define II 50000
#define DD 64
#define EE 2000000
#define LL 3
#define SCAN_B 1024
#define NBLK ((NN + SCAN_B - 1) / SCAN_B)   // 147

// -------- device scratch (no allocations allowed) --------
// g_deg is zero at program load AND re-zeroed by cleanup_kernel at the end of
// every kernel_launch call, so each call starts with deg == 0 deterministically.
__device__ float   g_curA[NN * DD];
__device__ float   g_curB[NN * DD];
__device__ float   g_curS[NN * DD];        // dis ⊙ cur, fp32 (layer1 gather operand)
__device__ float   g_gnn[NN * DD];
__device__ __half2 g_gnh[NN * 32];         // normalized gnn, fp16 (layer2 score gather)
__device__ float   g_invn[NN];
__device__ float   g_dis[NN];
__device__ int     g_deg[NN];
__device__ int     g_rowptr[NN + 1];
__device__ int     g_cursor[NN];
__device__ int     g_ecol[EE];
__device__ int     g_bsum[NBLK + 1];

// ---------------- setup kernels ----------------

// 4 edges per thread, int4 index loads, 4 atomics in flight
__global__ void hist_kernel(const int* __restrict__ rows) {
    int t = blockIdx.x * blockDim.x + threadIdx.x;
    if (t >= EE / 4) return;
    int4 r = __ldg(((const int4*)rows) + t);
    atomicAdd(&g_deg[r.x], 1);
    atomicAdd(&g_deg[r.y], 1);
    atomicAdd(&g_deg[r.z], 1);
    atomicAdd(&g_deg[r.w], 1);
}

// per-block inclusive scan of deg; block sums; dis
__global__ void scan1_kernel() {
    __shared__ int s[SCAN_B];
    int i = blockIdx.x * SCAN_B + threadIdx.x;
    int v = (i < NN) ? g_deg[i] : 0;
    if (i < NN) g_dis[i] = v > 0 ? rsqrtf((float)v) : 0.f;
    s[threadIdx.x] = v;
    __syncthreads();
    #pragma unroll
    for (int off = 1; off < SCAN_B; off <<= 1) {
        int t = (threadIdx.x >= off) ? s[threadIdx.x - off] : 0;
        __syncthreads();
        s[threadIdx.x] += t;
        __syncthreads();
    }
    if (i < NN) g_rowptr[i + 1] = s[threadIdx.x];
    if (threadIdx.x == SCAN_B - 1) g_bsum[blockIdx.x] = s[SCAN_B - 1];
}

// fused scan2+scan3: each block computes the needed bsum prefixes from smem
__global__ void scan3_kernel() {
    __shared__ int sb[NBLK];
    for (int t = threadIdx.x; t < NBLK; t += blockDim.x) sb[t] = g_bsum[t];
    __syncthreads();
    int i = blockIdx.x * blockDim.x + threadIdx.x;
    if (i == 0) g_rowptr[0] = 0;
    if (i < NN) {
        int b = i / SCAN_B;
        int off = 0;
        for (int k = 0; k < b; k++) off += sb[k];   // exclusive prefix of block sums
        int fin = g_rowptr[i + 1] + off;
        g_rowptr[i + 1] = fin;
        g_cursor[i] = fin - g_deg[i];
    }
}

// fused scatter + init (independent work; both need only scan results)
__global__ void scatter_init_kernel(const int* __restrict__ rows,
                                    const int* __restrict__ cols,
                                    const float* __restrict__ user_emb,
                                    const float* __restrict__ item_emb,
                                    float* __restrict__ out) {
    int gid = blockIdx.x * blockDim.x + threadIdx.x;
    // init part: one feature element per thread
    if (gid < NN * DD) {
        float v = (gid < UU * DD) ? user_emb[gid] : item_emb[gid - UU * DD];
        g_curA[gid] = v;
        g_curS[gid] = v * g_dis[gid >> 6];
        out[gid] = v;
    }
    // scatter part: 4 edges per thread for the first EE/4 threads
    if (gid < EE / 4) {
        int4 r = __ldg(((const int4*)rows) + gid);
        int4 c = __ldg(((const int4*)cols) + gid);
        int p0 = atomicAdd(&g_cursor[r.x], 1);
        int p1 = atomicAdd(&g_cursor[r.y], 1);
        int p2 = atomicAdd(&g_cursor[r.z], 1);
        int p3 = atomicAdd(&g_cursor[r.w], 1);
        g_ecol[p0] = c.x;
        g_ecol[p1] = c.y;
        g_ecol[p2] = c.z;
        g_ecol[p3] = c.w;
    }
}

// zero g_deg for the NEXT call (runs at end of every call)
__global__ void cleanup_kernel() {
    int i = blockIdx.x * blockDim.x + threadIdx.x;
    if (i < NN) g_deg[i] = 0;
}

// ---------------- per-layer kernels (R4 config, proven 684us) ----------------

__global__ void __launch_bounds__(256)
layer1_kernel(const float* __restrict__ curS) {
    int w = (blockIdx.x * blockDim.x + threadIdx.x) >> 5;
    int lane = threadIdx.x & 31;
    if (w >= NN) return;
    int start = g_rowptr[w];
    int end   = g_rowptr[w + 1];
    float ax0 = 0.f, ay0 = 0.f, ax1 = 0.f, ay1 = 0.f;
    int j = start;
    for (; j + 3 < end; j += 4) {
        int c0 = __ldg(g_ecol + j);
        int c1 = __ldg(g_ecol + j + 1);
        int c2 = __ldg(g_ecol + j + 2);
        int c3 = __ldg(g_ecol + j + 3);
        float2 v0 = __ldg(((const float2*)(curS + (size_t)c0 * DD)) + lane);
        float2 v1 = __ldg(((const float2*)(curS + (size_t)c1 * DD)) + lane);
        float2 v2 = __ldg(((const float2*)(curS + (size_t)c2 * DD)) + lane);
        float2 v3 = __ldg(((const float2*)(curS + (size_t)c3 * DD)) + lane);
        ax0 += v0.x + v2.x;  ay0 += v0.y + v2.y;
        ax1 += v1.x + v3.x;  ay1 += v1.y + v3.y;
    }
    for (; j < end; j++) {
        int c = __ldg(g_ecol + j);
        float2 v = __ldg(((const float2*)(curS + (size_t)c * DD)) + lane);
        ax0 += v.x;  ay0 += v.y;
    }
    float dr = g_dis[w];
    float ax = (ax0 + ax1) * dr;
    float ay = (ay0 + ay1) * dr;
    ((float2*)(g_gnn + (size_t)w * DD))[lane] = make_float2(ax, ay);
    float ss = ax * ax + ay * ay;
    #pragma unroll
    for (int o = 16; o > 0; o >>= 1) ss += __shfl_xor_sync(0xFFFFFFFFu, ss, o);
    float inv = 1.0f / fmaxf(sqrtf(ss), 1e-12f);
    if (lane == 0) g_invn[w] = inv;
    g_gnh[(size_t)w * 32 + lane] = __floats2half2_rn(ax * inv, ay * inv);
}

__global__ void __launch_bounds__(256)
layer2_kernel(const float* __restrict__ cur_old,
              float* __restrict__ cur_new,
              float* __restrict__ out, int layer) {
    int w = (blockIdx.x * blockDim.x + threadIdx.x) >> 5;
    int lane = threadIdx.x & 31;
    if (w >= NN) return;
    int start = g_rowptr[w];
    int end   = g_rowptr[w + 1];
    float2 gfull = ((const float2*)(g_gnn + (size_t)w * DD))[lane];
    float invr = g_invn[w];
    float grx = gfull.x * invr, gry = gfull.y * invr;

    float rowsum = 0.f, fx = 0.f, fy = 0.f;
    int j = start;
    for (; j + 3 < end; j += 4) {
        int c0 = __ldg(g_ecol + j);
        int c1 = __ldg(g_ecol + j + 1);
        int c2 = __ldg(g_ecol + j + 2);
        int c3 = __ldg(g_ecol + j + 3);
        float2 q0 = __half22float2(__ldg(g_gnh + (size_t)c0 * 32 + lane));
        float2 q1 = __half22float2(__ldg(g_gnh + (size_t)c1 * 32 + lane));
        float2 q2 = __half22float2(__ldg(g_gnh + (size_t)c2 * 32 + lane));
        float2 q3 = __half22float2(__ldg(g_gnh + (size_t)c3 * 32 + lane));
        float2 v0 = __ldg(((const float2*)(cur_old + (size_t)c0 * DD)) + lane);
        float2 v1 = __ldg(((const float2*)(cur_old + (size_t)c1 * DD)) + lane);
        float2 v2 = __ldg(((const float2*)(cur_old + (size_t)c2 * DD)) + lane);
        float2 v3 = __ldg(((const float2*)(cur_old + (size_t)c3 * DD)) + lane);
        float d0 = grx * q0.x + gry * q0.y;
        float d1 = grx * q1.x + gry * q1.y;
        float d2 = grx * q2.x + gry * q2.y;
        float d3 = grx * q3.x + gry * q3.y;
        #pragma unroll
        for (int o = 16; o > 0; o >>= 1) {
            d0 += __shfl_xor_sync(0xFFFFFFFFu, d0, o);
            d1 += __shfl_xor_sync(0xFFFFFFFFu, d1, o);
            d2 += __shfl_xor_sync(0xFFFFFFFFu, d2, o);
            d3 += __shfl_xor_sync(0xFFFFFFFFu, d3, o);
        }
        float s0 = fmaf(d0, 0.5f, 0.5f);
        float s1 = fmaf(d1, 0.5f, 0.5f);
        float s2 = fmaf(d2, 0.5f, 0.5f);
        float s3 = fmaf(d3, 0.5f, 0.5f);
        rowsum += (s0 + s1) + (s2 + s3);
        fx = fmaf(s0, v0.x, fx);  fy = fmaf(s0, v0.y, fy);
        fx = fmaf(s1, v1.x, fx);  fy = fmaf(s1, v1.y, fy);
        fx = fmaf(s2, v2.x, fx);  fy = fmaf(s2, v2.y, fy);
        fx = fmaf(s3, v3.x, fx);  fy = fmaf(s3, v3.y, fy);
    }
    for (; j < end; j++) {
        int c = __ldg(g_ecol + j);
        float2 q = __half22float2(__ldg(g_gnh + (size_t)c * 32 + lane));
        float2 v = __ldg(((const float2*)(cur_old + (size_t)c * DD)) + lane);
        float d = grx * q.x + gry * q.y;
        #pragma unroll
        for (int o = 16; o > 0; o >>= 1) d += __shfl_xor_sync(0xFFFFFFFFu, d, o);
        float s = fmaf(d, 0.5f, 0.5f);
        rowsum += s;
        fx = fmaf(s, v.x, fx);  fy = fmaf(s, v.y, fy);
    }

    float dinv = rowsum > 0.f ? 1.0f / rowsum : 0.f;
    fx *= dinv;
    fy *= dinv;

    // fine slice -> out (stacked: [acc(N,D)][user_fine(L,U,D)][item_fine(L,I,D)])
    size_t fpos;
    if (w < UU)
        fpos = (size_t)NN * DD + (size_t)layer * UU * DD + (size_t)w * DD;
    else
        fpos = (size_t)NN * DD + (size_t)LL * UU * DD + (size_t)layer * II * DD
             + (size_t)(w - UU) * DD;
    ((float2*)(out + fpos))[lane] = make_float2(fx, fy);

    float cx = gfull.x + fx, cy = gfull.y + fy;       // cur_next = gnn + fine
    ((float2*)(cur_new + (size_t)w * DD))[lane] = make_float2(cx, cy);

    float dr = g_dis[w];                               // curS_next = dis ⊙ cur_next
    ((float2*)(g_curS + (size_t)w * DD))[lane] = make_float2(cx * dr, cy * dr);

    float2* o = (float2*)(out + (size_t)w * DD);       // acc += cur_next
    float2 ov = o[lane];
    o[lane] = make_float2(ov.x + cx, ov.y + cy);
}

// ---------------- launch ----------------
extern "C" void kernel_launch(void* const* d_in, const int* in_sizes, int n_in,
                              void* d_out, int out_size) {
    const float* user_emb = (const float*)d_in[0];
    const float* item_emb = (const float*)d_in[1];
    const int*   rows     = (const int*)d_in[2];
    const int*   cols     = (const int*)d_in[3];
    float* out = (float*)d_out;

    void *p_curA, *p_curB, *p_curS;
    cudaGetSymbolAddress(&p_curA, g_curA);
    cudaGetSymbolAddress(&p_curB, g_curB);
    cudaGetSymbolAddress(&p_curS, g_curS);   // device address (NOT the host shadow!)

    cudaStream_t s = 0;
    const int TB = 256;
    const int grid_E4   = (EE / 4 + TB - 1) / TB;
    const int grid_N    = (NN + TB - 1) / TB;
    const int grid_ND   = (NN * DD + TB - 1) / TB;
    const int grid_RowW = (NN * 32 + TB - 1) / TB;   // warp-per-row

    // launch idx:        0                1            2             3
    hist_kernel<<<grid_E4, TB, 0, s>>>(rows);
    scan1_kernel<<<NBLK, SCAN_B, 0, s>>>();
    scan3_kernel<<<grid_N, TB, 0, s>>>();
    scatter_init_kernel<<<grid_ND, TB, 0, s>>>(rows, cols, user_emb, item_emb, out);

    float* bufA = (float*)p_curA;
    float* bufB = (float*)p_curB;
    for (int l = 0; l < LL; l++) {
        layer1_kernel<<<grid_RowW, TB, 0, s>>>((const float*)p_curS);  // idx 4 on l=0
        layer2_kernel<<<grid_RowW, TB, 0, s>>>(bufA, bufB, out, l);
        float* t = bufA; bufA = bufB; bufB = t;
    }
    cleanup_kernel<<<grid_N, TB, 0, s>>>();   // re-zero g_deg for the next call
}